// round 8
// baseline (speedup 1.0000x reference)
#include <cuda_runtime.h>
#include <cstdint>

typedef unsigned long long u64;
typedef unsigned int u32;

#define ROWS 8192
#define KDIM 3072
#define KHALF 1536
#define NOUT 64
#define KT   64                 // k per tile
#define NKT  24                 // tiles per K-half (1536/64)
#define STAGE_A 32768           // 128 rows * 64 f32
#define STAGE_B 16384           // 64 rows * 64 f32
#define STAGE   (STAGE_A + STAGE_B)
#define NSTAGE  3
#define SMEMSZ  (NSTAGE * STAGE)   // 147456

// ---- scratch (no allocation allowed) ----
__device__ __align__(16) float g_xwt[8 * NOUT * KDIM];     // B matrices, tf32-rounded
__device__ __align__(16) float g_cpart[2 * ROWS * NOUT];   // K-split partials
__device__ __align__(16) float g_zbuf[ROWS * NOUT];
__device__ __align__(16) float g_part[NOUT * 64];          // [k][cta]
__device__ __align__(16) float g_psq [NOUT * 64];

// ---- helpers ----
__device__ __forceinline__ u64 pack2(float a, float b){
    u64 r; asm("mov.b64 %0,{%1,%2};" : "=l"(r) : "f"(a), "f"(b)); return r;
}
__device__ __forceinline__ void unpack2(u64 v, float& a, float& b){
    asm("mov.b64 {%0,%1},%2;" : "=f"(a), "=f"(b) : "l"(v));
}
__device__ __forceinline__ u64 fma2(u64 a, u64 b, u64 c){
    u64 d; asm("fma.rn.f32x2 %0,%1,%2,%3;" : "=l"(d) : "l"(a), "l"(b), "l"(c)); return d;
}
__device__ __forceinline__ void cp16(char* smem_dst, const void* gsrc){
    unsigned s = (unsigned)__cvta_generic_to_shared(smem_dst);
    asm volatile("cp.async.cg.shared.global [%0], [%1], 16;" :: "r"(s), "l"(gsrc));
}
__device__ __forceinline__ u32 to_tf32(float f){
    u32 r; asm("cvt.rna.tf32.f32 %0,%1;" : "=r"(r) : "f"(f)); return r;
}
__device__ __forceinline__ void mma_tf32(float c[4], const u32 a[4], const u32 b[2]){
    asm volatile(
        "mma.sync.aligned.m16n8k8.row.col.f32.tf32.tf32.f32 "
        "{%0,%1,%2,%3}, {%4,%5,%6,%7}, {%8,%9}, {%0,%1,%2,%3};"
        : "+f"(c[0]), "+f"(c[1]), "+f"(c[2]), "+f"(c[3])
        : "r"(a[0]), "r"(a[1]), "r"(a[2]), "r"(a[3]), "r"(b[0]), "r"(b[1]));
}

// ============================================================================
// k_xw: XWT[b][n][m*3+j] = tf32( sum_f x[b,m,f] * Wc[n, j*32+f] )
// ============================================================================
__global__ __launch_bounds__(64)
void k_xw(const float* __restrict__ x, const float* __restrict__ W1,
          const float* __restrict__ W2)
{
    __shared__ __align__(16) float wcs[96];
    __shared__ u64 xsp[64][17];
    const int bidx = blockIdx.x;
    const int bb = bidx >> 6, n = bidx & 63;
    const int tid = threadIdx.x;

    const float* wr = (n < 32) ? (W1 + n * 96) : (W2 + (size_t)(n - 32) * 96);
    wcs[tid] = wr[tid];
    if (tid < 32) wcs[64 + tid] = wr[64 + tid];

    const float* xbp = x + (size_t)bb * 1024 * 32;
    float* outp = g_xwt + ((size_t)bb * NOUT + n) * KDIM;

    for (int ch = 0; ch < 16; ch++) {
        __syncthreads();
        #pragma unroll
        for (int i = 0; i < 8; i++) {
            int ml = (tid >> 3) + i * 8, fq = tid & 7;
            float4 v = *(const float4*)(xbp + (size_t)(ch * 64 + ml) * 32 + fq * 4);
            float* p = (float*)&xsp[ml][2 * fq];
            p[0] = v.x; p[1] = v.y; p[2] = v.z; p[3] = v.w;
        }
        __syncthreads();
        u64 xr[16];
        #pragma unroll
        for (int q = 0; q < 16; q++) xr[q] = xsp[tid][q];
        const u64* wcp = (const u64*)wcs;
        const int m = ch * 64 + tid;
        #pragma unroll
        for (int j = 0; j < 3; j++) {
            u64 a = 0ull;
            #pragma unroll
            for (int q = 0; q < 16; q++) a = fma2(wcp[j * 16 + q], xr[q], a);
            float lo, hi; unpack2(a, lo, hi);
            outp[m * 3 + j] = __uint_as_float(to_tf32(lo + hi));
        }
    }
}

// ============================================================================
// k_gemm: partial C[128,64] = A[128,1536] x B[64,1536]^T via mma.sync tf32
// grid 128 = (mblk 64) x (khalf 2), block 256 = 2 s-groups x 4 mma-warps
// ============================================================================
__global__ __launch_bounds__(256, 1)
void k_gemm(const float* __restrict__ WW)
{
    extern __shared__ __align__(1024) char smem[];
    const int tid  = threadIdx.x;
    const int warp = tid >> 5, lane = tid & 31;
    const int w4   = warp & 3;          // mma warp (M rows)
    const int sg   = warp >> 2;         // s-group: 0 -> s 0..3, 1 -> s 4..7
    const int g    = lane >> 2, t4 = lane & 3;
    const int kh   = blockIdx.x & 1;
    const int mblk = blockIdx.x >> 1;
    const int R0   = mblk * 128;
    const int bb   = mblk >> 3;
    const int koff = kh * KHALF;

    float acc[2][8][4];
    #pragma unroll
    for (int mt = 0; mt < 2; mt++)
        #pragma unroll
        for (int nt = 0; nt < 8; nt++)
            #pragma unroll
            for (int i = 0; i < 4; i++) acc[mt][nt][i] = 0.f;

    const float* Abase = WW + (size_t)R0 * KDIM + koff;
    const float* Bbase = g_xwt + (size_t)bb * NOUT * KDIM + koff;

    auto issue = [&](int t){
        char* sa = smem + (t % NSTAGE) * STAGE;
        char* sbm = sa + STAGE_A;
        const int k0 = t * KT;
        #pragma unroll
        for (int i = 0; i < 8; i++) {
            int c = tid + i * 256;                 // < 2048
            int rr = c >> 4, q = c & 15;
            cp16(sa + rr * 256 + ((q ^ (rr & 7)) * 16),
                 Abase + (size_t)rr * KDIM + k0 + q * 4);
        }
        #pragma unroll
        for (int i = 0; i < 4; i++) {
            int c = tid + i * 256;                 // < 1024
            int rr = c >> 4, q = c & 15;
            cp16(sbm + rr * 256 + ((q ^ (rr & 7)) * 16),
                 Bbase + (size_t)rr * KDIM + k0 + q * 4);
        }
        asm volatile("cp.async.commit_group;" ::: "memory");
    };

    issue(0); issue(1);

    const int xh = (g & 6) << 2;        // bits 3-4 of xor
    const int xl = (g & 1) << 2;        // bit 2 of xor
    const int kA = t4 ^ xl;
    const int kB = (t4 + 4) ^ xl;
    const int rb0 = (w4 * 32 + g) * 64;
    const int sbase = sg * 4;

    #pragma unroll 1
    for (int t = 0; t < NKT; t++) {
        if (t + 1 < NKT) asm volatile("cp.async.wait_group 1;" ::: "memory");
        else             asm volatile("cp.async.wait_group 0;" ::: "memory");
        __syncthreads();
        if (t + 2 < NKT) issue(t + 2);

        const float* As = (const float*)(smem + (t % NSTAGE) * STAGE);
        const u32*   Bs = (const u32*)  (smem + (t % NSTAGE) * STAGE + STAGE_A);

        #pragma unroll
        for (int si = 0; si < 4; si++) {
            const int s  = sbase + si;
            const int v  = (8 * s) ^ xh;
            const int o1 = v + kA, o2 = v + kB;
            u32 a[2][4];
            #pragma unroll
            for (int mt = 0; mt < 2; mt++) {
                const int rb = rb0 + mt * 1024;
                a[mt][0] = to_tf32(As[rb + o1]);
                a[mt][1] = to_tf32(As[rb + 512 + o1]);
                a[mt][2] = to_tf32(As[rb + o2]);
                a[mt][3] = to_tf32(As[rb + 512 + o2]);
            }
            u32 b[8][2];
            #pragma unroll
            for (int nt = 0; nt < 8; nt++) {
                const int nb = (nt * 8 + g) * 64;
                b[nt][0] = Bs[nb + o1];
                b[nt][1] = Bs[nb + o2];
            }
            #pragma unroll
            for (int mt = 0; mt < 2; mt++)
                #pragma unroll
                for (int nt = 0; nt < 8; nt++)
                    mma_tf32(acc[mt][nt], a[mt], b[nt]);
        }
    }

    // ---- merge s-group accumulators through smem, then write partial ----
    __syncthreads();                    // all cp.async consumed; reuse stage 0
    float4* cbuf = (float4*)smem;       // [128][17] float4 (68 floats/thread)
    if (sg == 1) {
        const float4* av = (const float4*)&acc[0][0][0];
        #pragma unroll
        for (int i = 0; i < 16; i++) cbuf[(tid - 128) * 17 + i] = av[i];
    }
    __syncthreads();
    if (sg == 0) {
        float4* av = (float4*)&acc[0][0][0];
        #pragma unroll
        for (int i = 0; i < 16; i++) {
            float4 o = cbuf[tid * 17 + i];
            av[i].x += o.x; av[i].y += o.y; av[i].z += o.z; av[i].w += o.w;
        }
        float* cp = g_cpart + (size_t)kh * ROWS * NOUT;
        #pragma unroll
        for (int mt = 0; mt < 2; mt++) {
            const int row = R0 + w4 * 32 + mt * 16 + g;
            #pragma unroll
            for (int nt = 0; nt < 8; nt++) {
                const int col = nt * 8 + 2 * t4;
                *(float2*)&cp[(size_t)row * 64 + col] =
                    make_float2(acc[mt][nt][0], acc[mt][nt][1]);
                *(float2*)&cp[(size_t)(row + 8) * 64 + col] =
                    make_float2(acc[mt][nt][2], acc[mt][nt][3]);
            }
        }
    }
}

// ============================================================================
// k_combine: z = c0 + c1 + bias (relu on first 32), zbuf + BN partials
// grid 64, block 256   (partials written TRANSPOSED: g_part[k][cta])
// ============================================================================
__global__ __launch_bounds__(256)
void k_combine(const float* __restrict__ b1, const float* __restrict__ b2)
{
    __shared__ float bias[64];
    __shared__ float ps[256], pq[256];
    const int tid = threadIdx.x;
    if (tid < 32)       bias[tid] = b1[tid];
    else if (tid < 64)  bias[tid] = b2[tid - 32];
    __syncthreads();

    const int k  = tid & 63;
    const int rh = tid >> 6;                  // 0..3
    const float bk = bias[k];
    float ls = 0.f, lsq = 0.f;
    const int base = blockIdx.x * 128;
    #pragma unroll 4
    for (int i = 0; i < 32; i++) {
        const size_t idx = (size_t)(base + rh + 4 * i) * 64 + k;
        float z = g_cpart[idx] + g_cpart[(size_t)ROWS * NOUT + idx] + bk;
        if (k < 32) z = fmaxf(z, 0.f);
        g_zbuf[idx] = z;
        ls += z; lsq += z * z;
    }
    ps[tid] = ls; pq[tid] = lsq;
    __syncthreads();
    if (tid < 64) {
        g_part[k * 64 + blockIdx.x] = ps[k] + ps[64 + k] + ps[128 + k] + ps[192 + k];
        g_psq [k * 64 + blockIdx.x] = pq[k] + pq[64 + k] + pq[128 + k] + pq[192 + k];
    }
}

// ============================================================================
// k_norm: per-block redundant stats (L2-hot 16KB) + normalize
// grid 64, block 256, 8 float4 per thread
// ============================================================================
__global__ __launch_bounds__(256)
void k_norm(const float* __restrict__ gamma, const float* __restrict__ beta,
            float* __restrict__ out)
{
    __shared__ float sc[64], sh[64];
    const int tid = threadIdx.x;
    if (tid < 64) {
        const float4* p4 = (const float4*)(g_part + tid * 64);
        const float4* q4 = (const float4*)(g_psq  + tid * 64);
        float s = 0.f, sq = 0.f;
        #pragma unroll
        for (int i = 0; i < 16; i++) {
            float4 a = p4[i], b = q4[i];
            s  += (a.x + a.y) + (a.z + a.w);
            sq += (b.x + b.y) + (b.z + b.w);
        }
        float mean = s / (float)ROWS;
        float var  = sq / (float)ROWS - mean * mean;
        float scale = gamma[tid] * rsqrtf(var + 1e-5f);
        sc[tid] = scale;
        sh[tid] = beta[tid] - mean * scale;
    }
    __syncthreads();
    #pragma unroll
    for (int it = 0; it < 8; it++) {
        int i = blockIdx.x * 2048 + it * 256 + tid;      // float4 index
        float4 z = ((const float4*)g_zbuf)[i];
        int kb = (i & 15) * 4;
        float4 o;
        o.x = z.x * sc[kb+0] + sh[kb+0];
        o.y = z.y * sc[kb+1] + sh[kb+1];
        o.z = z.z * sc[kb+2] + sh[kb+2];
        o.w = z.w * sc[kb+3] + sh[kb+3];
        ((float4*)out)[i] = o;
    }
}

extern "C" void kernel_launch(void* const* d_in, const int* in_sizes, int n_in,
                              void* d_out, int out_size)
{
    const float* WW    = (const float*)d_in[0];
    const float* x     = (const float*)d_in[1];
    const float* W1    = (const float*)d_in[2];
    const float* b1    = (const float*)d_in[3];
    const float* W2    = (const float*)d_in[4];
    const float* b2    = (const float*)d_in[5];
    const float* gamma = (const float*)d_in[6];
    const float* beta  = (const float*)d_in[7];
    float* out = (float*)d_out;

    cudaFuncSetAttribute(k_gemm, cudaFuncAttributeMaxDynamicSharedMemorySize, SMEMSZ);

    k_xw     <<<512, 64>>>(x, W1, W2);
    k_gemm   <<<128, 256, SMEMSZ>>>(WW);
    k_combine<<<64, 256>>>(b1, b2);
    k_norm   <<<64, 256>>>(gamma, beta, out);
}

// round 10
// speedup vs baseline: 1.0834x; 1.0834x over previous
#include <cuda_runtime.h>
#include <cstdint>

typedef unsigned long long u64;
typedef unsigned int u32;

#define ROWS 8192
#define KDIM 3072
#define KHALF 1536
#define NOUT 64
#define KT   64                 // k per tile
#define NKT  24                 // tiles per K-half (1536/64)
#define STAGE_A 32768           // 128 rows * 64 f32
#define STAGE_B 16384           // 64 rows * 64 f32
#define STAGE   (STAGE_A + STAGE_B)
#define NSTAGE  3
#define SMEMSZ  (NSTAGE * STAGE)   // 147456
#define NCOMB 256               // combine CTAs

// ---- scratch (no allocation allowed) ----
__device__ __align__(16) float g_xwt[8 * NOUT * KDIM];     // B matrices, tf32-rounded
__device__ __align__(16) float g_cpart[2 * ROWS * NOUT];   // K-split partials
__device__ __align__(16) float g_zbuf[ROWS * NOUT];
__device__ __align__(16) float g_part[NCOMB * NOUT];       // [cta][k]
__device__ __align__(16) float g_psq [NCOMB * NOUT];

// ---- helpers ----
__device__ __forceinline__ u64 pack2(float a, float b){
    u64 r; asm("mov.b64 %0,{%1,%2};" : "=l"(r) : "f"(a), "f"(b)); return r;
}
__device__ __forceinline__ void unpack2(u64 v, float& a, float& b){
    asm("mov.b64 {%0,%1},%2;" : "=f"(a), "=f"(b) : "l"(v));
}
__device__ __forceinline__ u64 fma2(u64 a, u64 b, u64 c){
    u64 d; asm("fma.rn.f32x2 %0,%1,%2,%3;" : "=l"(d) : "l"(a), "l"(b), "l"(c)); return d;
}
__device__ __forceinline__ void cp16(char* smem_dst, const void* gsrc){
    unsigned s = (unsigned)__cvta_generic_to_shared(smem_dst);
    asm volatile("cp.async.cg.shared.global [%0], [%1], 16;" :: "r"(s), "l"(gsrc));
}
__device__ __forceinline__ u32 to_tf32(float f){
    u32 r; asm("cvt.rna.tf32.f32 %0,%1;" : "=r"(r) : "f"(f)); return r;
}
__device__ __forceinline__ void mma_tf32(float c[4], const u32 a[4], const u32 b[2]){
    asm volatile(
        "mma.sync.aligned.m16n8k8.row.col.f32.tf32.tf32.f32 "
        "{%0,%1,%2,%3}, {%4,%5,%6,%7}, {%8,%9}, {%0,%1,%2,%3};"
        : "+f"(c[0]), "+f"(c[1]), "+f"(c[2]), "+f"(c[3])
        : "r"(a[0]), "r"(a[1]), "r"(a[2]), "r"(a[3]), "r"(b[0]), "r"(b[1]));
}

// ============================================================================
// k_xw: XWT[b][n][m*3+j] = tf32( sum_f x[b,m,f] * Wc[n, j*32+f] )
// ============================================================================
__global__ __launch_bounds__(64)
void k_xw(const float* __restrict__ x, const float* __restrict__ W1,
          const float* __restrict__ W2)
{
    __shared__ __align__(16) float wcs[96];
    __shared__ u64 xsp[64][17];
    const int bidx = blockIdx.x;
    const int bb = bidx >> 6, n = bidx & 63;
    const int tid = threadIdx.x;

    const float* wr = (n < 32) ? (W1 + n * 96) : (W2 + (size_t)(n - 32) * 96);
    wcs[tid] = wr[tid];
    if (tid < 32) wcs[64 + tid] = wr[64 + tid];

    const float* xbp = x + (size_t)bb * 1024 * 32;
    float* outp = g_xwt + ((size_t)bb * NOUT + n) * KDIM;

    for (int ch = 0; ch < 16; ch++) {
        __syncthreads();
        #pragma unroll
        for (int i = 0; i < 8; i++) {
            int ml = (tid >> 3) + i * 8, fq = tid & 7;
            float4 v = *(const float4*)(xbp + (size_t)(ch * 64 + ml) * 32 + fq * 4);
            float* p = (float*)&xsp[ml][2 * fq];
            p[0] = v.x; p[1] = v.y; p[2] = v.z; p[3] = v.w;
        }
        __syncthreads();
        u64 xr[16];
        #pragma unroll
        for (int q = 0; q < 16; q++) xr[q] = xsp[tid][q];
        const u64* wcp = (const u64*)wcs;
        const int m = ch * 64 + tid;
        #pragma unroll
        for (int j = 0; j < 3; j++) {
            u64 a = 0ull;
            #pragma unroll
            for (int q = 0; q < 16; q++) a = fma2(wcp[j * 16 + q], xr[q], a);
            float lo, hi; unpack2(a, lo, hi);
            outp[m * 3 + j] = __uint_as_float(to_tf32(lo + hi));
        }
    }
}

// ============================================================================
// k_gemm: partial C[128,64] = A[128,1536] x B[64,1536]^T via mma.sync tf32
// grid 128 = (mblk 64) x (khalf 2), block 512 = 4 s-groups x 4 mma-warps
// ============================================================================
__global__ __launch_bounds__(512, 1)
void k_gemm(const float* __restrict__ WW)
{
    extern __shared__ __align__(1024) char smem[];
    const int tid  = threadIdx.x;
    const int warp = tid >> 5, lane = tid & 31;
    const int w4   = warp & 3;          // mma warp (M rows)
    const int sg   = warp >> 2;         // s-group: handles s = 2*sg, 2*sg+1
    const int g    = lane >> 2, t4 = lane & 3;
    const int kh   = blockIdx.x & 1;
    const int mblk = blockIdx.x >> 1;
    const int R0   = mblk * 128;
    const int bb   = mblk >> 3;
    const int koff = kh * KHALF;

    float acc[2][8][4];
    #pragma unroll
    for (int mt = 0; mt < 2; mt++)
        #pragma unroll
        for (int nt = 0; nt < 8; nt++)
            #pragma unroll
            for (int i = 0; i < 4; i++) acc[mt][nt][i] = 0.f;

    const float* Abase = WW + (size_t)R0 * KDIM + koff;
    const float* Bbase = g_xwt + (size_t)bb * NOUT * KDIM + koff;

    auto issue = [&](int t){
        char* sa = smem + (t % NSTAGE) * STAGE;
        char* sbm = sa + STAGE_A;
        const int k0 = t * KT;
        #pragma unroll
        for (int i = 0; i < 4; i++) {
            int c = tid + i * 512;                 // < 2048
            int rr = c >> 4, q = c & 15;
            cp16(sa + rr * 256 + ((q ^ (rr & 7)) * 16),
                 Abase + (size_t)rr * KDIM + k0 + q * 4);
        }
        #pragma unroll
        for (int i = 0; i < 2; i++) {
            int c = tid + i * 512;                 // < 1024
            int rr = c >> 4, q = c & 15;
            cp16(sbm + rr * 256 + ((q ^ (rr & 7)) * 16),
                 Bbase + (size_t)rr * KDIM + k0 + q * 4);
        }
        asm volatile("cp.async.commit_group;" ::: "memory");
    };

    issue(0); issue(1);

    const int xh = (g & 6) << 2;        // bits 3-4 of xor
    const int xl = (g & 1) << 2;        // bit 2 of xor
    const int kA = t4 ^ xl;
    const int kB = (t4 + 4) ^ xl;
    const int rb0 = (w4 * 32 + g) * 64;
    const int sbase = sg * 2;

    #pragma unroll 1
    for (int t = 0; t < NKT; t++) {
        if (t + 1 < NKT) asm volatile("cp.async.wait_group 1;" ::: "memory");
        else             asm volatile("cp.async.wait_group 0;" ::: "memory");
        __syncthreads();
        if (t + 2 < NKT) issue(t + 2);

        const float* As = (const float*)(smem + (t % NSTAGE) * STAGE);
        const u32*   Bs = (const u32*)  (smem + (t % NSTAGE) * STAGE + STAGE_A);

        #pragma unroll
        for (int si = 0; si < 2; si++) {
            const int s  = sbase + si;
            const int v  = (8 * s) ^ xh;
            const int o1 = v + kA, o2 = v + kB;
            u32 a[2][4];
            #pragma unroll
            for (int mt = 0; mt < 2; mt++) {
                const int rb = rb0 + mt * 1024;
                a[mt][0] = to_tf32(As[rb + o1]);
                a[mt][1] = to_tf32(As[rb + 512 + o1]);
                a[mt][2] = to_tf32(As[rb + o2]);
                a[mt][3] = to_tf32(As[rb + 512 + o2]);
            }
            u32 b[8][2];
            #pragma unroll
            for (int nt = 0; nt < 8; nt++) {
                const int nb = (nt * 8 + g) * 64;
                b[nt][0] = Bs[nb + o1];
                b[nt][1] = Bs[nb + o2];
            }
            #pragma unroll
            for (int mt = 0; mt < 2; mt++)
                #pragma unroll
                for (int nt = 0; nt < 8; nt++)
                    mma_tf32(acc[mt][nt], a[mt], b[nt]);
        }
    }

    // ---- merge the 4 s-group accumulators through smem (tree reduce) ----
    __syncthreads();                    // all stages consumed; reuse as buffers
    float4* buf0 = (float4*)smem;                     // 128 x 17 float4
    float4* buf1 = (float4*)(smem + 36864);           // 128 x 17 float4
    const int sl = tid & 127;
    float4* av = (float4*)&acc[0][0][0];

    if (sg == 1) {
        for (int i = 0; i < 16; i++) buf0[sl * 17 + i] = av[i];
    } else if (sg == 3) {
        for (int i = 0; i < 16; i++) buf1[sl * 17 + i] = av[i];
    }
    __syncthreads();
    if (sg == 0) {
        for (int i = 0; i < 16; i++) {
            float4 o = buf0[sl * 17 + i];
            av[i].x += o.x; av[i].y += o.y; av[i].z += o.z; av[i].w += o.w;
        }
    } else if (sg == 2) {
        for (int i = 0; i < 16; i++) {
            float4 o = buf1[sl * 17 + i];
            av[i].x += o.x; av[i].y += o.y; av[i].z += o.z; av[i].w += o.w;
        }
    }
    __syncthreads();
    if (sg == 2) {
        for (int i = 0; i < 16; i++) buf0[sl * 17 + i] = av[i];
    }
    __syncthreads();
    if (sg == 0) {
        for (int i = 0; i < 16; i++) {
            float4 o = buf0[sl * 17 + i];
            av[i].x += o.x; av[i].y += o.y; av[i].z += o.z; av[i].w += o.w;
        }
        float* cp = g_cpart + (size_t)kh * ROWS * NOUT;
        #pragma unroll
        for (int mt = 0; mt < 2; mt++) {
            const int row = R0 + w4 * 32 + mt * 16 + g;
            #pragma unroll
            for (int nt = 0; nt < 8; nt++) {
                const int col = nt * 8 + 2 * t4;
                *(float2*)&cp[(size_t)row * 64 + col] =
                    make_float2(acc[mt][nt][0], acc[mt][nt][1]);
                *(float2*)&cp[(size_t)(row + 8) * 64 + col] =
                    make_float2(acc[mt][nt][2], acc[mt][nt][3]);
            }
        }
    }
}

// ============================================================================
// k_combine: z = c0 + c1 + bias (relu on first 32), zbuf + BN partials
// grid 256 (32 rows/CTA), block 256; partials g_part[cta][k]
// ============================================================================
__global__ __launch_bounds__(256)
void k_combine(const float* __restrict__ b1, const float* __restrict__ b2)
{
    __shared__ float bias[64];
    __shared__ float ps[256], pq[256];
    const int tid = threadIdx.x;
    if (tid < 32)       bias[tid] = b1[tid];
    else if (tid < 64)  bias[tid] = b2[tid - 32];
    __syncthreads();

    const int k  = tid & 63;
    const int rh = tid >> 6;                  // 0..3
    const float bk = bias[k];
    float ls = 0.f, lsq = 0.f;
    const int base = blockIdx.x * 32;
    #pragma unroll
    for (int i = 0; i < 8; i++) {
        const size_t idx = (size_t)(base + rh + 4 * i) * 64 + k;
        float z = g_cpart[idx] + g_cpart[(size_t)ROWS * NOUT + idx] + bk;
        if (k < 32) z = fmaxf(z, 0.f);
        g_zbuf[idx] = z;
        ls += z; lsq += z * z;
    }
    ps[tid] = ls; pq[tid] = lsq;
    __syncthreads();
    if (tid < 64) {
        g_part[blockIdx.x * 64 + k] = ps[k] + ps[64 + k] + ps[128 + k] + ps[192 + k];
        g_psq [blockIdx.x * 64 + k] = pq[k] + pq[64 + k] + pq[128 + k] + pq[192 + k];
    }
}

// ============================================================================
// k_norm: redundant per-block stats (coalesced partial read) + normalize
// grid 64, block 256
// ============================================================================
__global__ __launch_bounds__(256)
void k_norm(const float* __restrict__ gamma, const float* __restrict__ beta,
            float* __restrict__ out)
{
    __shared__ float sc[64], sh[64];
    __shared__ float rs[256], rq[256];
    const int tid = threadIdx.x;
    {
        const int k = tid & 63, qd = tid >> 6;     // quarter of CTAs
        float s = 0.f, sq = 0.f;
        #pragma unroll 8
        for (int c = qd * 64; c < qd * 64 + 64; c++) {
            s  += g_part[c * 64 + k];
            sq += g_psq [c * 64 + k];
        }
        rs[tid] = s; rq[tid] = sq;
    }
    __syncthreads();
    if (tid < 64) {
        float s  = rs[tid] + rs[64 + tid] + rs[128 + tid] + rs[192 + tid];
        float sq = rq[tid] + rq[64 + tid] + rq[128 + tid] + rq[192 + tid];
        float mean = s / (float)ROWS;
        float var  = sq / (float)ROWS - mean * mean;
        float scale = gamma[tid] * rsqrtf(var + 1e-5f);
        sc[tid] = scale;
        sh[tid] = beta[tid] - mean * scale;
    }
    __syncthreads();
    #pragma unroll
    for (int it = 0; it < 8; it++) {
        int i = blockIdx.x * 2048 + it * 256 + tid;      // float4 index
        float4 z = ((const float4*)g_zbuf)[i];
        int kb = (i & 15) * 4;
        float4 o;
        o.x = z.x * sc[kb+0] + sh[kb+0];
        o.y = z.y * sc[kb+1] + sh[kb+1];
        o.z = z.z * sc[kb+2] + sh[kb+2];
        o.w = z.w * sc[kb+3] + sh[kb+3];
        ((float4*)out)[i] = o;
    }
}

extern "C" void kernel_launch(void* const* d_in, const int* in_sizes, int n_in,
                              void* d_out, int out_size)
{
    const float* WW    = (const float*)d_in[0];
    const float* x     = (const float*)d_in[1];
    const float* W1    = (const float*)d_in[2];
    const float* b1    = (const float*)d_in[3];
    const float* W2    = (const float*)d_in[4];
    const float* b2    = (const float*)d_in[5];
    const float* gamma = (const float*)d_in[6];
    const float* beta  = (const float*)d_in[7];
    float* out = (float*)d_out;

    cudaFuncSetAttribute(k_gemm, cudaFuncAttributeMaxDynamicSharedMemorySize, SMEMSZ);

    k_xw     <<<512, 64>>>(x, W1, W2);
    k_gemm   <<<128, 512, SMEMSZ>>>(WW);
    k_combine<<<NCOMB, 256>>>(b1, b2);
    k_norm   <<<64, 256>>>(gamma, beta, out);
}

// round 11
// speedup vs baseline: 1.1858x; 1.0946x over previous
#include <cuda_runtime.h>
#include <cstdint>

typedef unsigned long long u64;
typedef unsigned int u32;

#define ROWS 8192
#define KDIM 3072
#define NOUT 64
#define KT   128                // k per tile
#define NKT  24                 // 3072/128
#define RPC  64                 // rows per CTA
#define NCTA 128                // gemm CTAs
#define STAGE_A 32768           // 64 rows * 128 f32
#define STAGE_B 32768           // 64 rows * 128 f32
#define STAGE   (STAGE_A + STAGE_B)
#define NSTAGE  3
#define SMEMSZ  (NSTAGE * STAGE)   // 196608

// ---- scratch (no allocation allowed) ----
__device__ __align__(16) float g_xwt[8 * NOUT * KDIM];     // B matrices, tf32-rounded
__device__ __align__(16) float g_zbuf[ROWS * NOUT];
__device__ __align__(16) float g_part[NCTA * NOUT];        // [cta][k]
__device__ __align__(16) float g_psq [NCTA * NOUT];

// ---- helpers ----
__device__ __forceinline__ u64 pack2(float a, float b){
    u64 r; asm("mov.b64 %0,{%1,%2};" : "=l"(r) : "f"(a), "f"(b)); return r;
}
__device__ __forceinline__ void unpack2(u64 v, float& a, float& b){
    asm("mov.b64 {%0,%1},%2;" : "=f"(a), "=f"(b) : "l"(v));
}
__device__ __forceinline__ u64 fma2(u64 a, u64 b, u64 c){
    u64 d; asm("fma.rn.f32x2 %0,%1,%2,%3;" : "=l"(d) : "l"(a), "l"(b), "l"(c)); return d;
}
__device__ __forceinline__ void cp16(char* smem_dst, const void* gsrc){
    unsigned s = (unsigned)__cvta_generic_to_shared(smem_dst);
    asm volatile("cp.async.cg.shared.global [%0], [%1], 16;" :: "r"(s), "l"(gsrc));
}
__device__ __forceinline__ u32 to_tf32(float f){
    u32 r; asm("cvt.rna.tf32.f32 %0,%1;" : "=r"(r) : "f"(f)); return r;
}
__device__ __forceinline__ void mma_tf32(float c[4], const u32 a[4], const u32 b[2]){
    asm volatile(
        "mma.sync.aligned.m16n8k8.row.col.f32.tf32.tf32.f32 "
        "{%0,%1,%2,%3}, {%4,%5,%6,%7}, {%8,%9}, {%0,%1,%2,%3};"
        : "+f"(c[0]), "+f"(c[1]), "+f"(c[2]), "+f"(c[3])
        : "r"(a[0]), "r"(a[1]), "r"(a[2]), "r"(a[3]), "r"(b[0]), "r"(b[1]));
}

// ============================================================================
// k_xw: XWT[b][n][m*3+j] = tf32( sum_f x[b,m,f] * Wc[n, j*32+f] )
// ============================================================================
__global__ __launch_bounds__(64)
void k_xw(const float* __restrict__ x, const float* __restrict__ W1,
          const float* __restrict__ W2)
{
    __shared__ __align__(16) float wcs[96];
    __shared__ u64 xsp[64][17];
    const int bidx = blockIdx.x;
    const int bb = bidx >> 6, n = bidx & 63;
    const int tid = threadIdx.x;

    const float* wr = (n < 32) ? (W1 + n * 96) : (W2 + (size_t)(n - 32) * 96);
    wcs[tid] = wr[tid];
    if (tid < 32) wcs[64 + tid] = wr[64 + tid];

    const float* xbp = x + (size_t)bb * 1024 * 32;
    float* outp = g_xwt + ((size_t)bb * NOUT + n) * KDIM;

    for (int ch = 0; ch < 16; ch++) {
        __syncthreads();
        #pragma unroll
        for (int i = 0; i < 8; i++) {
            int ml = (tid >> 3) + i * 8, fq = tid & 7;
            float4 v = *(const float4*)(xbp + (size_t)(ch * 64 + ml) * 32 + fq * 4);
            float* p = (float*)&xsp[ml][2 * fq];
            p[0] = v.x; p[1] = v.y; p[2] = v.z; p[3] = v.w;
        }
        __syncthreads();
        u64 xr[16];
        #pragma unroll
        for (int q = 0; q < 16; q++) xr[q] = xsp[tid][q];
        const u64* wcp = (const u64*)wcs;
        const int m = ch * 64 + tid;
        #pragma unroll
        for (int j = 0; j < 3; j++) {
            u64 a = 0ull;
            #pragma unroll
            for (int q = 0; q < 16; q++) a = fma2(wcp[j * 16 + q], xr[q], a);
            float lo, hi; unpack2(a, lo, hi);
            outp[m * 3 + j] = __uint_as_float(to_tf32(lo + hi));
        }
    }
}

// ============================================================================
// k_gemm: C[64,64] = A[64,3072] x B[64,3072]^T (tf32 mma.sync), fused epilogue
// grid 128, block 512 = 2 M-warps x 8 s-groups
// ============================================================================
__global__ __launch_bounds__(512, 1)
void k_gemm(const float* __restrict__ WW,
            const float* __restrict__ b1, const float* __restrict__ b2)
{
    extern __shared__ __align__(1024) char smem[];
    __shared__ float bias[64];
    __shared__ float ps[256], pq[256];
    const int tid  = threadIdx.x;
    const int warp = tid >> 5, lane = tid & 31;
    const int w2   = warp & 1;          // M-warp: rows w2*32 .. +31
    const int sg   = warp >> 1;         // s-group 0..7: s = 2*sg, 2*sg+1
    const int g    = lane >> 2, t4 = lane & 3;
    const int R0   = blockIdx.x * RPC;
    const int bb   = blockIdx.x >> 4;   // 16 CTAs per batch

    if (tid < 32)       bias[tid] = b1[tid];
    else if (tid < 64)  bias[tid] = b2[tid - 32];

    float acc[2][8][4];
    #pragma unroll
    for (int mt = 0; mt < 2; mt++)
        #pragma unroll
        for (int nt = 0; nt < 8; nt++)
            #pragma unroll
            for (int i = 0; i < 4; i++) acc[mt][nt][i] = 0.f;

    const float* Abase = WW + (size_t)R0 * KDIM;
    const float* Bbase = g_xwt + (size_t)bb * NOUT * KDIM;

    auto issue = [&](int t){
        char* sa = smem + (t % NSTAGE) * STAGE;
        char* sb = sa + STAGE_A;
        const int k0 = t * KT;
        #pragma unroll
        for (int i = 0; i < 4; i++) {
            int c = tid + i * 512;                 // < 2048
            int rr = c >> 5, cq = c & 31;
            cp16(sa + rr * 512 + ((cq ^ (rr & 7)) << 4),
                 Abase + (size_t)rr * KDIM + k0 + cq * 4);
        }
        #pragma unroll
        for (int i = 0; i < 4; i++) {
            int c = tid + i * 512;                 // < 2048
            int rr = c >> 5, cq = c & 31;
            cp16(sb + rr * 512 + ((cq ^ (rr & 7)) << 4),
                 Bbase + (size_t)rr * KDIM + k0 + cq * 4);
        }
        asm volatile("cp.async.commit_group;" ::: "memory");
    };

    issue(0); issue(1);

    #pragma unroll 1
    for (int t = 0; t < NKT; t++) {
        if (t + 1 < NKT) asm volatile("cp.async.wait_group 1;" ::: "memory");
        else             asm volatile("cp.async.wait_group 0;" ::: "memory");
        __syncthreads();
        if (t + 2 < NKT) issue(t + 2);

        const float* As = (const float*)(smem + (t % NSTAGE) * STAGE);
        const u32*   Bs = (const u32*)  (smem + (t % NSTAGE) * STAGE + STAGE_A);

        #pragma unroll
        for (int si = 0; si < 2; si++) {
            const int s  = sg * 2 + si;                 // 0..15
            const int c0 = ((2 * s)     ^ g) * 4 + t4;  // float offset of k t4
            const int c1 = ((2 * s + 1) ^ g) * 4 + t4;  // float offset of k 4+t4
            u32 a[2][4];
            #pragma unroll
            for (int mt = 0; mt < 2; mt++) {
                const int ro = (w2 * 32 + mt * 16 + g) * 128;
                a[mt][0] = to_tf32(As[ro + c0]);
                a[mt][1] = to_tf32(As[ro + 1024 + c0]);    // row + 8
                a[mt][2] = to_tf32(As[ro + c1]);
                a[mt][3] = to_tf32(As[ro + 1024 + c1]);
            }
            u32 b[8][2];
            #pragma unroll
            for (int nt = 0; nt < 8; nt++) {
                const int nb = (nt * 8 + g) * 128;
                b[nt][0] = Bs[nb + c0];
                b[nt][1] = Bs[nb + c1];
            }
            #pragma unroll
            for (int mt = 0; mt < 2; mt++)
                #pragma unroll
                for (int nt = 0; nt < 8; nt++)
                    mma_tf32(acc[mt][nt], a[mt], b[nt]);
        }
    }

    // ---- tree-merge 8 s-groups through smem ----
    __syncthreads();
    const int sl = tid & 63;                         // slot within s-group
    float4* av = (float4*)&acc[0][0][0];             // 16 float4 per thread
    // 4 regions of 64 threads x 16 float4 (+1 pad) = 4 x 16.25KB
    auto region = [&](int rgn)->float4* { return (float4*)smem + rgn * 1088; };

    if (sg >= 4) { float4* bf = region(sg - 4);
        for (int i = 0; i < 16; i++) bf[sl * 17 + i] = av[i]; }
    __syncthreads();
    if (sg < 4)  { float4* bf = region(sg);
        for (int i = 0; i < 16; i++) { float4 o = bf[sl * 17 + i];
            av[i].x += o.x; av[i].y += o.y; av[i].z += o.z; av[i].w += o.w; } }
    __syncthreads();
    if (sg == 2 || sg == 3) { float4* bf = region(sg - 2);
        for (int i = 0; i < 16; i++) bf[sl * 17 + i] = av[i]; }
    __syncthreads();
    if (sg < 2)  { float4* bf = region(sg);
        for (int i = 0; i < 16; i++) { float4 o = bf[sl * 17 + i];
            av[i].x += o.x; av[i].y += o.y; av[i].z += o.z; av[i].w += o.w; } }
    __syncthreads();
    if (sg == 1) { float4* bf = region(0);
        for (int i = 0; i < 16; i++) bf[sl * 17 + i] = av[i]; }
    __syncthreads();

    // ---- sg0 (64 threads) finalizes: bias + relu + zbuf + zs ----
    float* zs = (float*)(smem + 72704);              // 64 x 66 floats (16.9KB)
    if (sg == 0) {
        float4* bf = region(0);
        for (int i = 0; i < 16; i++) { float4 o = bf[sl * 17 + i];
            av[i].x += o.x; av[i].y += o.y; av[i].z += o.z; av[i].w += o.w; }
        #pragma unroll
        for (int mt = 0; mt < 2; mt++) {
            const int r0 = w2 * 32 + mt * 16 + g;    // and r0+8
            #pragma unroll
            for (int nt = 0; nt < 8; nt++) {
                const int col = nt * 8 + 2 * t4;
                float z0 = acc[mt][nt][0] + bias[col];
                float z1 = acc[mt][nt][1] + bias[col + 1];
                float z2 = acc[mt][nt][2] + bias[col];
                float z3 = acc[mt][nt][3] + bias[col + 1];
                if (nt < 4) { z0 = fmaxf(z0, 0.f); z1 = fmaxf(z1, 0.f);
                              z2 = fmaxf(z2, 0.f); z3 = fmaxf(z3, 0.f); }
                *(float2*)&g_zbuf[(size_t)(R0 + r0) * 64 + col]     = make_float2(z0, z1);
                *(float2*)&g_zbuf[(size_t)(R0 + r0 + 8) * 64 + col] = make_float2(z2, z3);
                zs[r0 * 66 + col] = z0; zs[r0 * 66 + col + 1] = z1;
                zs[(r0 + 8) * 66 + col] = z2; zs[(r0 + 8) * 66 + col + 1] = z3;
            }
        }
    }
    __syncthreads();

    // ---- BN partials over this CTA's 64 rows ----
    if (tid < 256) {
        const int k = tid & 63, qd = tid >> 6;
        float s = 0.f, sq = 0.f;
        #pragma unroll
        for (int r = qd * 16; r < qd * 16 + 16; r++) {
            float v = zs[r * 66 + k];
            s += v; sq += v * v;
        }
        ps[tid] = s; pq[tid] = sq;
    }
    __syncthreads();
    if (tid < 64) {
        g_part[blockIdx.x * 64 + tid] = ps[tid] + ps[64 + tid] + ps[128 + tid] + ps[192 + tid];
        g_psq [blockIdx.x * 64 + tid] = pq[tid] + pq[64 + tid] + pq[128 + tid] + pq[192 + tid];
    }
}

// ============================================================================
// k_norm: redundant per-block stats (32KB L2-hot) + normalize
// grid 256, block 256
// ============================================================================
__global__ __launch_bounds__(256)
void k_norm(const float* __restrict__ gamma, const float* __restrict__ beta,
            float* __restrict__ out)
{
    __shared__ float sc[64], sh[64];
    __shared__ float rs[256], rq[256];
    const int tid = threadIdx.x;
    {
        const int k = tid & 63, qd = tid >> 6;     // quarter of the 128 CTAs
        float s = 0.f, sq = 0.f;
        #pragma unroll 8
        for (int c = qd * 32; c < qd * 32 + 32; c++) {
            s  += g_part[c * 64 + k];
            sq += g_psq [c * 64 + k];
        }
        rs[tid] = s; rq[tid] = sq;
    }
    __syncthreads();
    if (tid < 64) {
        float s  = rs[tid] + rs[64 + tid] + rs[128 + tid] + rs[192 + tid];
        float sq = rq[tid] + rq[64 + tid] + rq[128 + tid] + rq[192 + tid];
        float mean = s / (float)ROWS;
        float var  = sq / (float)ROWS - mean * mean;
        float scale = gamma[tid] * rsqrtf(var + 1e-5f);
        sc[tid] = scale;
        sh[tid] = beta[tid] - mean * scale;
    }
    __syncthreads();
    #pragma unroll
    for (int it = 0; it < 2; it++) {
        int i = blockIdx.x * 512 + it * 256 + tid;       // float4 index, 131072 total
        float4 z = ((const float4*)g_zbuf)[i];
        int kb = (i & 15) * 4;
        float4 o;
        o.x = z.x * sc[kb+0] + sh[kb+0];
        o.y = z.y * sc[kb+1] + sh[kb+1];
        o.z = z.z * sc[kb+2] + sh[kb+2];
        o.w = z.w * sc[kb+3] + sh[kb+3];
        ((float4*)out)[i] = o;
    }
}

extern "C" void kernel_launch(void* const* d_in, const int* in_sizes, int n_in,
                              void* d_out, int out_size)
{
    const float* WW    = (const float*)d_in[0];
    const float* x     = (const float*)d_in[1];
    const float* W1    = (const float*)d_in[2];
    const float* b1    = (const float*)d_in[3];
    const float* W2    = (const float*)d_in[4];
    const float* b2    = (const float*)d_in[5];
    const float* gamma = (const float*)d_in[6];
    const float* beta  = (const float*)d_in[7];
    float* out = (float*)d_out;

    cudaFuncSetAttribute(k_gemm, cudaFuncAttributeMaxDynamicSharedMemorySize, SMEMSZ);

    k_xw   <<<512, 64>>>(x, W1, W2);
    k_gemm <<<NCTA, 512, SMEMSZ>>>(WW, b1, b2);
    k_norm <<<256, 256>>>(gamma, beta, out);
}

// round 12
// speedup vs baseline: 1.3587x; 1.1458x over previous
#include <cuda_runtime.h>
#include <cstdint>

typedef unsigned long long u64;
typedef unsigned int u32;

#define ROWS 8192
#define KDIM 3072
#define NOUT 64
#define KT   128                // k per tile
#define NKT  24                 // 3072/128
#define RPC  64                 // rows per CTA
#define NCTA 128                // gemm CTAs
#define STAGE_A 32768           // 64 rows * 128 f32
#define STAGE_B 32768           // 64 rows * 128 f32
#define STAGE   (STAGE_A + STAGE_B)
#define NSTAGE  3
#define SMEMSZ  (NSTAGE * STAGE)   // 196608

// ---- scratch (no allocation allowed) ----
__device__ __align__(16) float g_xwt[8 * NOUT * KDIM];     // B matrices, tf32-rounded
__device__ __align__(16) float g_zbuf[ROWS * NOUT];
__device__ __align__(16) float g_part[NCTA * NOUT];        // [cta][k]
__device__ __align__(16) float g_psq [NCTA * NOUT];

// ---- helpers ----
__device__ __forceinline__ void cp16(char* smem_dst, const void* gsrc){
    unsigned s = (unsigned)__cvta_generic_to_shared(smem_dst);
    asm volatile("cp.async.cg.shared.global [%0], [%1], 16;" :: "r"(s), "l"(gsrc));
}
__device__ __forceinline__ u32 to_tf32(float f){
    u32 r; asm("cvt.rna.tf32.f32 %0,%1;" : "=r"(r) : "f"(f)); return r;
}
__device__ __forceinline__ void mma_tf32(float c[4], const u32 a[4], const u32 b[2]){
    asm volatile(
        "mma.sync.aligned.m16n8k8.row.col.f32.tf32.tf32.f32 "
        "{%0,%1,%2,%3}, {%4,%5,%6,%7}, {%8,%9}, {%0,%1,%2,%3};"
        : "+f"(c[0]), "+f"(c[1]), "+f"(c[2]), "+f"(c[3])
        : "r"(a[0]), "r"(a[1]), "r"(a[2]), "r"(a[3]), "r"(b[0]), "r"(b[1]));
}

// ============================================================================
// k_xw: XWT[b][n][m*3+j] = tf32( sum_f x[b,m,f] * Wc[n, j*32+f] )
// grid 128 = (b 8, mchunk 16), block 256 = (n 64, mq 4)
// ============================================================================
__global__ __launch_bounds__(256)
void k_xw(const float* __restrict__ x, const float* __restrict__ W1,
          const float* __restrict__ W2)
{
    __shared__ float xs[64][33];       // [m][f], bank = (m+f)%32
    __shared__ float ws[64][97];       // [n][c], bank = (n+c)%32
    const int bb = blockIdx.x >> 4;
    const int ch = blockIdx.x & 15;
    const int tid = threadIdx.x;

    for (int i = tid; i < 64 * 96; i += 256) {
        int n = i / 96, c = i % 96;
        ws[n][c] = (n < 32) ? W1[n * 96 + c] : W2[(size_t)(n - 32) * 96 + c];
    }
    {
        const float4* xb = (const float4*)(x + ((size_t)bb * 1024 + ch * 64) * 32);
        #pragma unroll
        for (int i = tid; i < 512; i += 256) {
            float4 v = xb[i];
            int m = i >> 3, fq = (i & 7) * 4;
            xs[m][fq + 0] = v.x; xs[m][fq + 1] = v.y;
            xs[m][fq + 2] = v.z; xs[m][fq + 3] = v.w;
        }
    }
    __syncthreads();

    const int n = tid >> 2, mq = tid & 3;
    float* outp = g_xwt + ((size_t)bb * NOUT + n) * KDIM + ch * 192;
    const float* wn = &ws[n][0];
    #pragma unroll 2
    for (int i = 0; i < 16; i++) {
        const int m = mq * 16 + i;
        float a0 = 0.f, a1 = 0.f, a2 = 0.f;
        #pragma unroll
        for (int f = 0; f < 32; f++) {
            float xv = xs[m][f];
            a0 = fmaf(xv, wn[f],      a0);
            a1 = fmaf(xv, wn[32 + f], a1);
            a2 = fmaf(xv, wn[64 + f], a2);
        }
        outp[m * 3 + 0] = __uint_as_float(to_tf32(a0));
        outp[m * 3 + 1] = __uint_as_float(to_tf32(a1));
        outp[m * 3 + 2] = __uint_as_float(to_tf32(a2));
    }
}

// ============================================================================
// k_gemm: C[64,64] = A[64,3072] x B[64,3072]^T (tf32 mma.sync), fused epilogue
// grid 128, block 512 = 2 M-warps x 8 s-groups
// ============================================================================
__global__ __launch_bounds__(512, 1)
void k_gemm(const float* __restrict__ WW,
            const float* __restrict__ b1, const float* __restrict__ b2)
{
    extern __shared__ __align__(1024) char smem[];
    __shared__ float bias[64];
    __shared__ float ps[256], pq[256];
    const int tid  = threadIdx.x;
    const int warp = tid >> 5, lane = tid & 31;
    const int w2   = warp & 1;          // M-warp: rows w2*32 .. +31
    const int sg   = warp >> 1;         // s-group 0..7: s = 2*sg, 2*sg+1
    const int g    = lane >> 2, t4 = lane & 3;
    const int R0   = blockIdx.x * RPC;
    const int bb   = blockIdx.x >> 4;   // 16 CTAs per batch

    if (tid < 32)       bias[tid] = b1[tid];
    else if (tid < 64)  bias[tid] = b2[tid - 32];

    float acc[2][8][4];
    #pragma unroll
    for (int mt = 0; mt < 2; mt++)
        #pragma unroll
        for (int nt = 0; nt < 8; nt++)
            #pragma unroll
            for (int i = 0; i < 4; i++) acc[mt][nt][i] = 0.f;

    const float* Abase = WW + (size_t)R0 * KDIM;
    const float* Bbase = g_xwt + (size_t)bb * NOUT * KDIM;

    auto issue = [&](int t){
        char* sa = smem + (t % NSTAGE) * STAGE;
        char* sb = sa + STAGE_A;
        const int k0 = t * KT;
        #pragma unroll
        for (int i = 0; i < 4; i++) {
            int c = tid + i * 512;                 // < 2048
            int rr = c >> 5, cq = c & 31;
            cp16(sa + rr * 512 + ((cq ^ (rr & 7)) << 4),
                 Abase + (size_t)rr * KDIM + k0 + cq * 4);
        }
        #pragma unroll
        for (int i = 0; i < 4; i++) {
            int c = tid + i * 512;                 // < 2048
            int rr = c >> 5, cq = c & 31;
            cp16(sb + rr * 512 + ((cq ^ (rr & 7)) << 4),
                 Bbase + (size_t)rr * KDIM + k0 + cq * 4);
        }
        asm volatile("cp.async.commit_group;" ::: "memory");
    };

    issue(0); issue(1);

    #pragma unroll 1
    for (int t = 0; t < NKT; t++) {
        if (t + 1 < NKT) asm volatile("cp.async.wait_group 1;" ::: "memory");
        else             asm volatile("cp.async.wait_group 0;" ::: "memory");
        __syncthreads();
        if (t + 2 < NKT) issue(t + 2);

        const float* As = (const float*)(smem + (t % NSTAGE) * STAGE);
        const u32*   Bs = (const u32*)  (smem + (t % NSTAGE) * STAGE + STAGE_A);

        #pragma unroll
        for (int si = 0; si < 2; si++) {
            const int s  = sg * 2 + si;                 // 0..15
            const int c0 = ((2 * s)     ^ g) * 4 + t4;  // float offset of k t4
            const int c1 = ((2 * s + 1) ^ g) * 4 + t4;  // float offset of k 4+t4
            u32 a[2][4];
            #pragma unroll
            for (int mt = 0; mt < 2; mt++) {
                const int ro = (w2 * 32 + mt * 16 + g) * 128;
                a[mt][0] = to_tf32(As[ro + c0]);
                a[mt][1] = to_tf32(As[ro + 1024 + c0]);    // row + 8
                a[mt][2] = to_tf32(As[ro + c1]);
                a[mt][3] = to_tf32(As[ro + 1024 + c1]);
            }
            u32 b[8][2];
            #pragma unroll
            for (int nt = 0; nt < 8; nt++) {
                const int nb = (nt * 8 + g) * 128;
                b[nt][0] = Bs[nb + c0];
                b[nt][1] = Bs[nb + c1];
            }
            #pragma unroll
            for (int mt = 0; mt < 2; mt++)
                #pragma unroll
                for (int nt = 0; nt < 8; nt++)
                    mma_tf32(acc[mt][nt], a[mt], b[nt]);
        }
    }

    // ---- tree-merge 8 s-groups through smem ----
    __syncthreads();
    const int sl = tid & 63;                         // slot within s-group
    float4* av = (float4*)&acc[0][0][0];             // 16 float4 per thread
    auto region = [&](int rgn)->float4* { return (float4*)smem + rgn * 1088; };

    if (sg >= 4) { float4* bf = region(sg - 4);
        for (int i = 0; i < 16; i++) bf[sl * 17 + i] = av[i]; }
    __syncthreads();
    if (sg < 4)  { float4* bf = region(sg);
        for (int i = 0; i < 16; i++) { float4 o = bf[sl * 17 + i];
            av[i].x += o.x; av[i].y += o.y; av[i].z += o.z; av[i].w += o.w; } }
    __syncthreads();
    if (sg == 2 || sg == 3) { float4* bf = region(sg - 2);
        for (int i = 0; i < 16; i++) bf[sl * 17 + i] = av[i]; }
    __syncthreads();
    if (sg < 2)  { float4* bf = region(sg);
        for (int i = 0; i < 16; i++) { float4 o = bf[sl * 17 + i];
            av[i].x += o.x; av[i].y += o.y; av[i].z += o.z; av[i].w += o.w; } }
    __syncthreads();
    if (sg == 1) { float4* bf = region(0);
        for (int i = 0; i < 16; i++) bf[sl * 17 + i] = av[i]; }
    __syncthreads();

    // ---- sg0 (64 threads) finalizes: bias + relu + zbuf + zs ----
    float* zs = (float*)(smem + 72704);              // 64 x 66 floats
    if (sg == 0) {
        float4* bf = region(0);
        for (int i = 0; i < 16; i++) { float4 o = bf[sl * 17 + i];
            av[i].x += o.x; av[i].y += o.y; av[i].z += o.z; av[i].w += o.w; }
        #pragma unroll
        for (int mt = 0; mt < 2; mt++) {
            const int r0 = w2 * 32 + mt * 16 + g;    // and r0+8
            #pragma unroll
            for (int nt = 0; nt < 8; nt++) {
                const int col = nt * 8 + 2 * t4;
                float z0 = acc[mt][nt][0] + bias[col];
                float z1 = acc[mt][nt][1] + bias[col + 1];
                float z2 = acc[mt][nt][2] + bias[col];
                float z3 = acc[mt][nt][3] + bias[col + 1];
                if (nt < 4) { z0 = fmaxf(z0, 0.f); z1 = fmaxf(z1, 0.f);
                              z2 = fmaxf(z2, 0.f); z3 = fmaxf(z3, 0.f); }
                *(float2*)&g_zbuf[(size_t)(R0 + r0) * 64 + col]     = make_float2(z0, z1);
                *(float2*)&g_zbuf[(size_t)(R0 + r0 + 8) * 64 + col] = make_float2(z2, z3);
                zs[r0 * 66 + col] = z0; zs[r0 * 66 + col + 1] = z1;
                zs[(r0 + 8) * 66 + col] = z2; zs[(r0 + 8) * 66 + col + 1] = z3;
            }
        }
    }
    __syncthreads();

    // ---- BN partials over this CTA's 64 rows ----
    if (tid < 256) {
        const int k = tid & 63, qd = tid >> 6;
        float s = 0.f, sq = 0.f;
        #pragma unroll
        for (int r = qd * 16; r < qd * 16 + 16; r++) {
            float v = zs[r * 66 + k];
            s += v; sq += v * v;
        }
        ps[tid] = s; pq[tid] = sq;
    }
    __syncthreads();
    if (tid < 64) {
        g_part[blockIdx.x * 64 + tid] = ps[tid] + ps[64 + tid] + ps[128 + tid] + ps[192 + tid];
        g_psq [blockIdx.x * 64 + tid] = pq[tid] + pq[64 + tid] + pq[128 + tid] + pq[192 + tid];
    }
}

// ============================================================================
// k_norm: redundant per-block stats (32KB L2-hot) + normalize
// grid 256, block 256
// ============================================================================
__global__ __launch_bounds__(256)
void k_norm(const float* __restrict__ gamma, const float* __restrict__ beta,
            float* __restrict__ out)
{
    __shared__ float sc[64], sh[64];
    __shared__ float rs[256], rq[256];
    const int tid = threadIdx.x;
    {
        const int k = tid & 63, qd = tid >> 6;     // quarter of the 128 CTAs
        float s = 0.f, sq = 0.f;
        #pragma unroll 8
        for (int c = qd * 32; c < qd * 32 + 32; c++) {
            s  += g_part[c * 64 + k];
            sq += g_psq [c * 64 + k];
        }
        rs[tid] = s; rq[tid] = sq;
    }
    __syncthreads();
    if (tid < 64) {
        float s  = rs[tid] + rs[64 + tid] + rs[128 + tid] + rs[192 + tid];
        float sq = rq[tid] + rq[64 + tid] + rq[128 + tid] + rq[192 + tid];
        float mean = s / (float)ROWS;
        float var  = sq / (float)ROWS - mean * mean;
        float scale = gamma[tid] * rsqrtf(var + 1e-5f);
        sc[tid] = scale;
        sh[tid] = beta[tid] - mean * scale;
    }
    __syncthreads();
    #pragma unroll
    for (int it = 0; it < 2; it++) {
        int i = blockIdx.x * 512 + it * 256 + tid;       // float4 index, 131072 total
        float4 z = ((const float4*)g_zbuf)[i];
        int kb = (i & 15) * 4;
        float4 o;
        o.x = z.x * sc[kb+0] + sh[kb+0];
        o.y = z.y * sc[kb+1] + sh[kb+1];
        o.z = z.z * sc[kb+2] + sh[kb+2];
        o.w = z.w * sc[kb+3] + sh[kb+3];
        ((float4*)out)[i] = o;
    }
}

extern "C" void kernel_launch(void* const* d_in, const int* in_sizes, int n_in,
                              void* d_out, int out_size)
{
    const float* WW    = (const float*)d_in[0];
    const float* x     = (const float*)d_in[1];
    const float* W1    = (const float*)d_in[2];
    const float* b1    = (const float*)d_in[3];
    const float* W2    = (const float*)d_in[4];
    const float* b2    = (const float*)d_in[5];
    const float* gamma = (const float*)d_in[6];
    const float* beta  = (const float*)d_in[7];
    float* out = (float*)d_out;

    cudaFuncSetAttribute(k_gemm, cudaFuncAttributeMaxDynamicSharedMemorySize, SMEMSZ);

    k_xw   <<<128, 256>>>(x, W1, W2);
    k_gemm <<<NCTA, 512, SMEMSZ>>>(WW, b1, b2);
    k_norm <<<256, 256>>>(gamma, beta, out);
}

// round 13
// speedup vs baseline: 1.4409x; 1.0605x over previous
#include <cuda_runtime.h>
#include <cstdint>

typedef unsigned long long u64;
typedef unsigned int u32;

#define ROWS 8192
#define KDIM 3072
#define NOUT 64
#define KT   128                // k per tile
#define NKT  24                 // 3072/128
#define RPC  64                 // rows per CTA
#define NCTA 128                // gemm CTAs
#define STAGE_A 32768           // 64 rows * 128 f32
#define STAGE_B 32768           // 64 rows * 128 f32
#define STAGE   (STAGE_A + STAGE_B)
#define NSTAGE  3
#define SMEMSZ  (NSTAGE * STAGE)   // 196608
#define XW_SMEM (25600 + 9216 + 50176)   // ws + xs + stage = 84992

// ---- scratch (no allocation allowed) ----
__device__ __align__(16) float g_xwt[8 * NOUT * KDIM];     // B matrices, tf32-rounded
__device__ __align__(16) float g_zbuf[ROWS * NOUT];
__device__ __align__(16) float g_part[NCTA * NOUT];        // [cta][k]
__device__ __align__(16) float g_psq [NCTA * NOUT];

// ---- helpers ----
__device__ __forceinline__ void cp16(char* smem_dst, const void* gsrc){
    unsigned s = (unsigned)__cvta_generic_to_shared(smem_dst);
    asm volatile("cp.async.cg.shared.global [%0], [%1], 16;" :: "r"(s), "l"(gsrc));
}
__device__ __forceinline__ u32 to_tf32(float f){
    u32 r; asm("cvt.rna.tf32.f32 %0,%1;" : "=r"(r) : "f"(f)); return r;
}
__device__ __forceinline__ void mma_tf32(float c[4], const u32 a[4], const u32 b[2]){
    asm volatile(
        "mma.sync.aligned.m16n8k8.row.col.f32.tf32.tf32.f32 "
        "{%0,%1,%2,%3}, {%4,%5,%6,%7}, {%8,%9}, {%0,%1,%2,%3};"
        : "+f"(c[0]), "+f"(c[1]), "+f"(c[2]), "+f"(c[3])
        : "r"(a[0]), "r"(a[1]), "r"(a[2]), "r"(a[3]), "r"(b[0]), "r"(b[1]));
}

// ============================================================================
// k_xw: XWT[b][n][m*3+j] = tf32( sum_f x[b,m,f] * Wc[n, j*32+f] )
// grid 128 = (b 8, mchunk 16 of 64 m), block 256 = (n 64, mq 4)
// ============================================================================
__global__ __launch_bounds__(256)
void k_xw(const float* __restrict__ x, const float* __restrict__ W1,
          const float* __restrict__ W2)
{
    extern __shared__ __align__(16) char xsm[];
    float4* ws4 = (float4*)xsm;                   // [64 n][25] (24 used)
    float4* xs4 = (float4*)(xsm + 25600);         // [64 m][9]  (8 used, xor swz)
    float*  stg = (float*)(xsm + 25600 + 9216);   // [64 n][196] (192 used)
    const int bb = blockIdx.x >> 4;
    const int ch = blockIdx.x & 15;
    const int tid = threadIdx.x;

    // fill ws: 1536 float4 (W rows are 384B -> 16B aligned)
    for (int i = tid; i < 1536; i += 256) {
        int n = i / 24, c = i % 24;
        const float4* src = (n < 32) ? (const float4*)(W1 + n * 96)
                                     : (const float4*)(W2 + (size_t)(n - 32) * 96);
        ws4[n * 25 + c] = src[c];
    }
    // fill xs: 512 float4, col swizzled by m>>4
    {
        const float4* xb = (const float4*)(x + ((size_t)bb * 1024 + ch * 64) * 32);
        for (int i = tid; i < 512; i += 256) {
            int m = i >> 3, fq = i & 7;
            xs4[m * 9 + (fq ^ (m >> 4))] = xb[i];
        }
    }
    __syncthreads();

    const int n = tid >> 2, mq = tid & 3;
    const float4* wn4 = ws4 + n * 25;
    #pragma unroll 1
    for (int mg = 0; mg < 4; mg++) {
        const int m0 = mq * 16 + mg * 4;
        float a[4][3];
        #pragma unroll
        for (int mi = 0; mi < 4; mi++) { a[mi][0] = a[mi][1] = a[mi][2] = 0.f; }
        #pragma unroll
        for (int fq = 0; fq < 8; fq++) {
            float4 w0 = wn4[fq];
            float4 w1 = wn4[8 + fq];
            float4 w2 = wn4[16 + fq];
            #pragma unroll
            for (int mi = 0; mi < 4; mi++) {
                float4 xv = xs4[(m0 + mi) * 9 + (fq ^ mq)];
                a[mi][0] = fmaf(xv.x, w0.x, fmaf(xv.y, w0.y, fmaf(xv.z, w0.z, fmaf(xv.w, w0.w, a[mi][0]))));
                a[mi][1] = fmaf(xv.x, w1.x, fmaf(xv.y, w1.y, fmaf(xv.z, w1.z, fmaf(xv.w, w1.w, a[mi][1]))));
                a[mi][2] = fmaf(xv.x, w2.x, fmaf(xv.y, w2.y, fmaf(xv.z, w2.z, fmaf(xv.w, w2.w, a[mi][2]))));
            }
        }
        #pragma unroll
        for (int mi = 0; mi < 4; mi++) {
            const int col = (m0 + mi) * 3;
            stg[n * 196 + col + 0] = __uint_as_float(to_tf32(a[mi][0]));
            stg[n * 196 + col + 1] = __uint_as_float(to_tf32(a[mi][1]));
            stg[n * 196 + col + 2] = __uint_as_float(to_tf32(a[mi][2]));
        }
    }
    __syncthreads();

    // coalesced writeback: [64 n][192 floats] = 3072 float4
    float* outb = g_xwt + (size_t)bb * NOUT * KDIM + ch * 192;
    for (int i = tid; i < 3072; i += 256) {
        int nn = i / 48, c = i % 48;
        float4 v = *(const float4*)&stg[nn * 196 + c * 4];
        *(float4*)&outb[(size_t)nn * KDIM + c * 4] = v;
    }
}

// ============================================================================
// k_gemm: C[64,64] = A[64,3072] x B[64,3072]^T (tf32 mma.sync), fused epilogue
// grid 128, block 512 = 2 M-warps x 8 s-groups   (UNCHANGED from 50.5us best)
// ============================================================================
__global__ __launch_bounds__(512, 1)
void k_gemm(const float* __restrict__ WW,
            const float* __restrict__ b1, const float* __restrict__ b2)
{
    extern __shared__ __align__(1024) char smem[];
    __shared__ float bias[64];
    __shared__ float ps[256], pq[256];
    const int tid  = threadIdx.x;
    const int warp = tid >> 5, lane = tid & 31;
    const int w2   = warp & 1;          // M-warp: rows w2*32 .. +31
    const int sg   = warp >> 1;         // s-group 0..7: s = 2*sg, 2*sg+1
    const int g    = lane >> 2, t4 = lane & 3;
    const int R0   = blockIdx.x * RPC;
    const int bb   = blockIdx.x >> 4;   // 16 CTAs per batch

    if (tid < 32)       bias[tid] = b1[tid];
    else if (tid < 64)  bias[tid] = b2[tid - 32];

    float acc[2][8][4];
    #pragma unroll
    for (int mt = 0; mt < 2; mt++)
        #pragma unroll
        for (int nt = 0; nt < 8; nt++)
            #pragma unroll
            for (int i = 0; i < 4; i++) acc[mt][nt][i] = 0.f;

    const float* Abase = WW + (size_t)R0 * KDIM;
    const float* Bbase = g_xwt + (size_t)bb * NOUT * KDIM;

    auto issue = [&](int t){
        char* sa = smem + (t % NSTAGE) * STAGE;
        char* sb = sa + STAGE_A;
        const int k0 = t * KT;
        #pragma unroll
        for (int i = 0; i < 4; i++) {
            int c = tid + i * 512;                 // < 2048
            int rr = c >> 5, cq = c & 31;
            cp16(sa + rr * 512 + ((cq ^ (rr & 7)) << 4),
                 Abase + (size_t)rr * KDIM + k0 + cq * 4);
        }
        #pragma unroll
        for (int i = 0; i < 4; i++) {
            int c = tid + i * 512;                 // < 2048
            int rr = c >> 5, cq = c & 31;
            cp16(sb + rr * 512 + ((cq ^ (rr & 7)) << 4),
                 Bbase + (size_t)rr * KDIM + k0 + cq * 4);
        }
        asm volatile("cp.async.commit_group;" ::: "memory");
    };

    issue(0); issue(1);

    #pragma unroll 1
    for (int t = 0; t < NKT; t++) {
        if (t + 1 < NKT) asm volatile("cp.async.wait_group 1;" ::: "memory");
        else             asm volatile("cp.async.wait_group 0;" ::: "memory");
        __syncthreads();
        if (t + 2 < NKT) issue(t + 2);

        const float* As = (const float*)(smem + (t % NSTAGE) * STAGE);
        const u32*   Bs = (const u32*)  (smem + (t % NSTAGE) * STAGE + STAGE_A);

        #pragma unroll
        for (int si = 0; si < 2; si++) {
            const int s  = sg * 2 + si;                 // 0..15
            const int c0 = ((2 * s)     ^ g) * 4 + t4;
            const int c1 = ((2 * s + 1) ^ g) * 4 + t4;
            u32 a[2][4];
            #pragma unroll
            for (int mt = 0; mt < 2; mt++) {
                const int ro = (w2 * 32 + mt * 16 + g) * 128;
                a[mt][0] = to_tf32(As[ro + c0]);
                a[mt][1] = to_tf32(As[ro + 1024 + c0]);
                a[mt][2] = to_tf32(As[ro + c1]);
                a[mt][3] = to_tf32(As[ro + 1024 + c1]);
            }
            u32 b[8][2];
            #pragma unroll
            for (int nt = 0; nt < 8; nt++) {
                const int nb = (nt * 8 + g) * 128;
                b[nt][0] = Bs[nb + c0];
                b[nt][1] = Bs[nb + c1];
            }
            #pragma unroll
            for (int mt = 0; mt < 2; mt++)
                #pragma unroll
                for (int nt = 0; nt < 8; nt++)
                    mma_tf32(acc[mt][nt], a[mt], b[nt]);
        }
    }

    // ---- tree-merge 8 s-groups through smem ----
    __syncthreads();
    const int sl = tid & 63;
    float4* av = (float4*)&acc[0][0][0];
    auto region = [&](int rgn)->float4* { return (float4*)smem + rgn * 1088; };

    if (sg >= 4) { float4* bf = region(sg - 4);
        for (int i = 0; i < 16; i++) bf[sl * 17 + i] = av[i]; }
    __syncthreads();
    if (sg < 4)  { float4* bf = region(sg);
        for (int i = 0; i < 16; i++) { float4 o = bf[sl * 17 + i];
            av[i].x += o.x; av[i].y += o.y; av[i].z += o.z; av[i].w += o.w; } }
    __syncthreads();
    if (sg == 2 || sg == 3) { float4* bf = region(sg - 2);
        for (int i = 0; i < 16; i++) bf[sl * 17 + i] = av[i]; }
    __syncthreads();
    if (sg < 2)  { float4* bf = region(sg);
        for (int i = 0; i < 16; i++) { float4 o = bf[sl * 17 + i];
            av[i].x += o.x; av[i].y += o.y; av[i].z += o.z; av[i].w += o.w; } }
    __syncthreads();
    if (sg == 1) { float4* bf = region(0);
        for (int i = 0; i < 16; i++) bf[sl * 17 + i] = av[i]; }
    __syncthreads();

    // ---- sg0 (64 threads) finalizes: bias + relu + zbuf + zs ----
    float* zs = (float*)(smem + 72704);              // 64 x 66 floats
    if (sg == 0) {
        float4* bf = region(0);
        for (int i = 0; i < 16; i++) { float4 o = bf[sl * 17 + i];
            av[i].x += o.x; av[i].y += o.y; av[i].z += o.z; av[i].w += o.w; }
        #pragma unroll
        for (int mt = 0; mt < 2; mt++) {
            const int r0 = w2 * 32 + mt * 16 + g;
            #pragma unroll
            for (int nt = 0; nt < 8; nt++) {
                const int col = nt * 8 + 2 * t4;
                float z0 = acc[mt][nt][0] + bias[col];
                float z1 = acc[mt][nt][1] + bias[col + 1];
                float z2 = acc[mt][nt][2] + bias[col];
                float z3 = acc[mt][nt][3] + bias[col + 1];
                if (nt < 4) { z0 = fmaxf(z0, 0.f); z1 = fmaxf(z1, 0.f);
                              z2 = fmaxf(z2, 0.f); z3 = fmaxf(z3, 0.f); }
                *(float2*)&g_zbuf[(size_t)(R0 + r0) * 64 + col]     = make_float2(z0, z1);
                *(float2*)&g_zbuf[(size_t)(R0 + r0 + 8) * 64 + col] = make_float2(z2, z3);
                zs[r0 * 66 + col] = z0; zs[r0 * 66 + col + 1] = z1;
                zs[(r0 + 8) * 66 + col] = z2; zs[(r0 + 8) * 66 + col + 1] = z3;
            }
        }
    }
    __syncthreads();

    // ---- BN partials over this CTA's 64 rows ----
    if (tid < 256) {
        const int k = tid & 63, qd = tid >> 6;
        float s = 0.f, sq = 0.f;
        #pragma unroll
        for (int r = qd * 16; r < qd * 16 + 16; r++) {
            float v = zs[r * 66 + k];
            s += v; sq += v * v;
        }
        ps[tid] = s; pq[tid] = sq;
    }
    __syncthreads();
    if (tid < 64) {
        g_part[blockIdx.x * 64 + tid] = ps[tid] + ps[64 + tid] + ps[128 + tid] + ps[192 + tid];
        g_psq [blockIdx.x * 64 + tid] = pq[tid] + pq[64 + tid] + pq[128 + tid] + pq[192 + tid];
    }
}

// ============================================================================
// k_norm: redundant per-block stats (32KB L2-hot) + normalize
// grid 256, block 256   (UNCHANGED)
// ============================================================================
__global__ __launch_bounds__(256)
void k_norm(const float* __restrict__ gamma, const float* __restrict__ beta,
            float* __restrict__ out)
{
    __shared__ float sc[64], sh[64];
    __shared__ float rs[256], rq[256];
    const int tid = threadIdx.x;
    {
        const int k = tid & 63, qd = tid >> 6;
        float s = 0.f, sq = 0.f;
        #pragma unroll 8
        for (int c = qd * 32; c < qd * 32 + 32; c++) {
            s  += g_part[c * 64 + k];
            sq += g_psq [c * 64 + k];
        }
        rs[tid] = s; rq[tid] = sq;
    }
    __syncthreads();
    if (tid < 64) {
        float s  = rs[tid] + rs[64 + tid] + rs[128 + tid] + rs[192 + tid];
        float sq = rq[tid] + rq[64 + tid] + rq[128 + tid] + rq[192 + tid];
        float mean = s / (float)ROWS;
        float var  = sq / (float)ROWS - mean * mean;
        float scale = gamma[tid] * rsqrtf(var + 1e-5f);
        sc[tid] = scale;
        sh[tid] = beta[tid] - mean * scale;
    }
    __syncthreads();
    #pragma unroll
    for (int it = 0; it < 2; it++) {
        int i = blockIdx.x * 512 + it * 256 + tid;
        float4 z = ((const float4*)g_zbuf)[i];
        int kb = (i & 15) * 4;
        float4 o;
        o.x = z.x * sc[kb+0] + sh[kb+0];
        o.y = z.y * sc[kb+1] + sh[kb+1];
        o.z = z.z * sc[kb+2] + sh[kb+2];
        o.w = z.w * sc[kb+3] + sh[kb+3];
        ((float4*)out)[i] = o;
    }
}

extern "C" void kernel_launch(void* const* d_in, const int* in_sizes, int n_in,
                              void* d_out, int out_size)
{
    const float* WW    = (const float*)d_in[0];
    const float* x     = (const float*)d_in[1];
    const float* W1    = (const float*)d_in[2];
    const float* b1    = (const float*)d_in[3];
    const float* W2    = (const float*)d_in[4];
    const float* b2    = (const float*)d_in[5];
    const float* gamma = (const float*)d_in[6];
    const float* beta  = (const float*)d_in[7];
    float* out = (float*)d_out;

    cudaFuncSetAttribute(k_xw,   cudaFuncAttributeMaxDynamicSharedMemorySize, XW_SMEM);
    cudaFuncSetAttribute(k_gemm, cudaFuncAttributeMaxDynamicSharedMemorySize, SMEMSZ);

    k_xw   <<<128, 256, XW_SMEM>>>(x, W1, W2);
    k_gemm <<<NCTA, 512, SMEMSZ>>>(WW, b1, b2);
    k_norm <<<256, 256>>>(gamma, beta, out);
}